// round 5
// baseline (speedup 1.0000x reference)
#include <cuda_runtime.h>
#include <math.h>

#define BATCH 8
#define HF    128
#define PIX   (HF*HF)
#define NOG   384
#define NIMP  96
#define NPTS  128
#define INC   512
#define HID2  256
#define KFEAT 514
#define KFP   528
#define COUT  2
#define NROWS (BATCH*NPTS) // 1024

// ---------------- scratch ----------------
__device__ float g_points[BATCH*NPTS*2];
__device__ float g_feat  [NROWS*KFP];
__device__ float g_t1    [NROWS*INC];
__device__ float g_h1    [NROWS*INC];
__device__ float g_t2    [NROWS*HID2];

// ---------------- bilinear helper ----------------
struct Bilin { int l00,l10,l01,l11; float w00,w10,w01,w11; };

__device__ __forceinline__ Bilin make_bilin(float px, float py) {
    Bilin r;
    float gx = ((2.0f*px - 1.0f + 1.0f)*(float)HF - 1.0f)*0.5f;
    float gy = ((2.0f*py - 1.0f + 1.0f)*(float)HF - 1.0f)*0.5f;
    float x0f = floorf(gx), y0f = floorf(gy);
    float wx1 = gx - x0f,  wy1 = gy - y0f;
    float wx0 = 1.0f - wx1, wy0 = 1.0f - wy1;
    int x0 = (int)x0f, y0 = (int)y0f;
    int x1 = x0 + 1,   y1 = y0 + 1;
    bool vx0 = (x0 >= 0) && (x0 <= HF-1);
    bool vx1 = (x1 >= 0) && (x1 <= HF-1);
    bool vy0 = (y0 >= 0) && (y0 <= HF-1);
    bool vy1 = (y1 >= 0) && (y1 <= HF-1);
    int x0c = min(max(x0,0),HF-1), x1c = min(max(x1,0),HF-1);
    int y0c = min(max(y0,0),HF-1), y1c = min(max(y1,0),HF-1);
    r.l00 = y0c*HF + x0c;  r.l10 = y0c*HF + x1c;
    r.l01 = y1c*HF + x0c;  r.l11 = y1c*HF + x1c;
    r.w00 = (vx0 && vy0) ? wx0*wy0 : 0.0f;
    r.w10 = (vx1 && vy0) ? wx1*wy0 : 0.0f;
    r.w01 = (vx0 && vy1) ? wx0*wy1 : 0.0f;
    r.w11 = (vx1 && vy1) ? wx1*wy1 : 0.0f;
    return r;
}

// ---------------- K1: sampling points ----------------
__global__ void __launch_bounds__(NOG) k_points(
    const float* __restrict__ out, const float* __restrict__ over_gen,
    const float* __restrict__ rand_point, float* __restrict__ pts_out)
{
    int b = blockIdx.x, tid = threadIdx.x;
    __shared__ float s_unc[NOG];
    const float* ob = out + (size_t)b*2*PIX;

    float px = over_gen[((size_t)b*NOG + tid)*2 + 0];
    float py = over_gen[((size_t)b*NOG + tid)*2 + 1];
    {
        Bilin bl = make_bilin(px, py);
        float a00 = ob[bl.l00], b00 = ob[PIX + bl.l00];
        float a10 = ob[bl.l10], b10 = ob[PIX + bl.l10];
        float a01 = ob[bl.l01], b01 = ob[PIX + bl.l01];
        float a11 = ob[bl.l11], b11 = ob[PIX + bl.l11];
        float og0 = bl.w00*fmaxf(a00,b00) + bl.w10*fmaxf(a10,b10)
                  + bl.w01*fmaxf(a01,b01) + bl.w11*fmaxf(a11,b11);
        float og1 = bl.w00*fminf(a00,b00) + bl.w10*fminf(a10,b10)
                  + bl.w01*fminf(a01,b01) + bl.w11*fminf(a11,b11);
        s_unc[tid] = og1 - og0;
    }
    __syncthreads();
    {
        float u = s_unc[tid];
        int rank = 0;
        #pragma unroll 8
        for (int j = 0; j < NOG; j++) {
            float uj = s_unc[j];
            rank += (uj > u) || (uj == u && j < tid);   // stable
        }
        if (rank < NIMP) {
            float2 p = make_float2(px, py);
            ((float2*)g_points)[b*NPTS + rank] = p;
            ((float2*)pts_out )[b*NPTS + rank] = p;
        }
    }
    if (tid < 16) {
        float2 z = make_float2(0.f, 0.f);
        ((float2*)g_points)[b*NPTS + NIMP + tid] = z;
        ((float2*)pts_out )[b*NPTS + NIMP + tid] = z;
        float2 rp = ((const float2*)rand_point)[b*16 + tid];
        ((float2*)g_points)[b*NPTS + NIMP + 16 + tid] = rp;
        ((float2*)pts_out )[b*NPTS + NIMP + 16 + tid] = rp;
    }
}

// ---------------- K2: gather feat rows ----------------
__global__ void __launch_bounds__(128) k_feat(
    const float* __restrict__ out, const float* __restrict__ res2)
{
    int idx = blockIdx.x;            // b*128 + n
    int b = idx >> 7;
    int tid = threadIdx.x;
    float2 p = ((const float2*)g_points)[idx];
    Bilin bl = make_bilin(p.x, p.y);
    const float* rb = res2 + (size_t)b*INC*PIX;
    float* frow = g_feat + (size_t)idx*KFP;

    #pragma unroll 4
    for (int c = tid; c < INC; c += 128) {
        const float* pp = rb + (size_t)c*PIX;
        frow[2 + c] = bl.w00*pp[bl.l00] + bl.w10*pp[bl.l10]
                    + bl.w01*pp[bl.l01] + bl.w11*pp[bl.l11];
    }
    if (tid < 2) {
        const float* pp = out + (size_t)(b*2 + tid)*PIX;
        frow[tid] = bl.w00*pp[bl.l00] + bl.w10*pp[bl.l10]
                  + bl.w01*pp[bl.l01] + bl.w11*pp[bl.l11];
    }
    if (tid >= 2 && tid < 16) frow[512 + tid] = 0.0f;
}

// ---------------- packed-f32x2 SGEMM + bias, double-buffered ---------------
// C[M,N] = A[M,KP(zeros beyond KREAL)] @ W[KREAL,N] + bias
// Accumulators packed over M-pairs; W duplicated {w,w} in shared.
#define FMA2(d,a,b) asm("fma.rn.f32x2 %0, %1, %2, %3;" \
                        : "=l"(d) : "l"(a), "l"(b), "l"(d))

template<int KREAL, int KP, int LDA, int N, int BM, int TM>
__global__ void __launch_bounds__(256) k_gemm(
    const float* __restrict__ A, const float* __restrict__ W,
    const float* __restrict__ bias, float* __restrict__ C)
{
    constexpr int BK = 16, BN = 64, TN = 4;
    constexpr int KT = KP / BK;
    constexpr int PM = TM / 2;               // M-pairs per thread
    __shared__ float sA [2][BK][BM + 4];
    __shared__ float sWd[2][BK][BN*2];       // duplicated pairs

    int tid = threadIdx.x;
    int tx = tid & 15, ty = tid >> 4;
    int row0 = blockIdx.y * BM, col0 = blockIdx.x * BN;

    int a_m = tid >> 2, a_k = (tid & 3) * 4;
    int w_k = tid >> 4, w_n = (tid & 15) * 4;
    const bool aload = (BM * 4 == 256) || (tid < BM * 4);

    float4 av = make_float4(0,0,0,0), wv;
    if (aload) av = *(const float4*)&A[(size_t)(row0 + a_m)*LDA + a_k];
    wv = (w_k < KREAL) ? *(const float4*)&W[(size_t)w_k*N + col0 + w_n]
                       : make_float4(0,0,0,0);
    if (aload) {
        sA[0][a_k+0][a_m] = av.x; sA[0][a_k+1][a_m] = av.y;
        sA[0][a_k+2][a_m] = av.z; sA[0][a_k+3][a_m] = av.w;
    }
    *(float4*)&sWd[0][w_k][2*w_n+0] = make_float4(wv.x, wv.x, wv.y, wv.y);
    *(float4*)&sWd[0][w_k][2*w_n+4] = make_float4(wv.z, wv.z, wv.w, wv.w);
    __syncthreads();

    unsigned long long acc2[PM][TN];
    #pragma unroll
    for (int p = 0; p < PM; p++)
        #pragma unroll
        for (int j = 0; j < TN; j++) acc2[p][j] = 0ull;

    for (int t = 0; t < KT; t++) {
        int buf = t & 1;
        if (t + 1 < KT) {
            int k0 = (t + 1) * BK;
            if (aload) av = *(const float4*)&A[(size_t)(row0 + a_m)*LDA + k0 + a_k];
            int kg = k0 + w_k;
            wv = (kg < KREAL) ? *(const float4*)&W[(size_t)kg*N + col0 + w_n]
                              : make_float4(0,0,0,0);
        }
        #pragma unroll
        for (int kk = 0; kk < BK; kk++) {
            unsigned long long ap[PM];
            if (PM == 2) {
                ulonglong2 aa = *(const ulonglong2*)&sA[buf][kk][ty*TM];
                ap[0] = aa.x; ap[1] = aa.y;
            } else {
                ap[0] = *(const unsigned long long*)&sA[buf][kk][ty*TM];
            }
            ulonglong2 wA = *(const ulonglong2*)&sWd[buf][kk][tx*8];
            ulonglong2 wB = *(const ulonglong2*)&sWd[buf][kk][tx*8+4];
            unsigned long long wd[TN] = {wA.x, wA.y, wB.x, wB.y};
            #pragma unroll
            for (int p = 0; p < PM; p++)
                #pragma unroll
                for (int j = 0; j < TN; j++)
                    FMA2(acc2[p][j], ap[p], wd[j]);
        }
        if (t + 1 < KT) {
            int nb = buf ^ 1;
            if (aload) {
                sA[nb][a_k+0][a_m] = av.x; sA[nb][a_k+1][a_m] = av.y;
                sA[nb][a_k+2][a_m] = av.z; sA[nb][a_k+3][a_m] = av.w;
            }
            *(float4*)&sWd[nb][w_k][2*w_n+0] = make_float4(wv.x, wv.x, wv.y, wv.y);
            *(float4*)&sWd[nb][w_k][2*w_n+4] = make_float4(wv.z, wv.z, wv.w, wv.w);
            __syncthreads();
        }
    }

    float4 bv = *(const float4*)&bias[col0 + tx*4];
    #pragma unroll
    for (int p = 0; p < PM; p++) {
        float lo[TN], hi[TN];
        #pragma unroll
        for (int j = 0; j < TN; j++)
            asm("mov.b64 {%0, %1}, %2;" : "=f"(lo[j]), "=f"(hi[j]) : "l"(acc2[p][j]));
        float4 v0 = make_float4(lo[0]+bv.x, lo[1]+bv.y, lo[2]+bv.z, lo[3]+bv.w);
        float4 v1 = make_float4(hi[0]+bv.x, hi[1]+bv.y, hi[2]+bv.z, hi[3]+bv.w);
        *(float4*)&C[(size_t)(row0 + ty*TM + 2*p + 0)*N + col0 + tx*4] = v0;
        *(float4*)&C[(size_t)(row0 + ty*TM + 2*p + 1)*N + col0 + tx*4] = v1;
    }
}

// ---------------- block reduce (128 threads / 4 warps) ---------------------
__device__ __forceinline__ float blk_reduce(float v, float* s, int tid) {
    int lane = tid & 31, warp = tid >> 5;
    #pragma unroll
    for (int o = 16; o; o >>= 1) v += __shfl_xor_sync(0xffffffff, v, o);
    if (lane == 0) s[warp] = v;
    __syncthreads();
    float r = s[0] + s[1] + s[2] + s[3];
    __syncthreads();
    return r;
}

// ---------------- K_ln1: LN + exact GELU (block per row) -------------------
__global__ void __launch_bounds__(128) k_ln1(
    const float* __restrict__ Xr, const float* __restrict__ gamma,
    const float* __restrict__ beta, float* __restrict__ Y)
{
    __shared__ float s[4];
    int row = blockIdx.x, tid = threadIdx.x;
    float4 t = ((const float4*)(Xr + (size_t)row*INC))[tid];
    float sum = blk_reduce(t.x + t.y + t.z + t.w, s, tid);
    float m = sum * (1.0f/INC);
    float dx = t.x-m, dy = t.y-m, dz = t.z-m, dw = t.w-m;
    float var = blk_reduce(dx*dx + dy*dy + dz*dz + dw*dw, s, tid);
    float inv = rsqrtf(var * (1.0f/INC) + 1e-5f);
    float4 gg = ((const float4*)gamma)[tid];
    float4 ee = ((const float4*)beta)[tid];
    float4 o4; float z;
    z = dx*inv*gg.x + ee.x; o4.x = 0.5f*z*(1.0f + erff(z*0.70710678118654752440f));
    z = dy*inv*gg.y + ee.y; o4.y = 0.5f*z*(1.0f + erff(z*0.70710678118654752440f));
    z = dz*inv*gg.z + ee.z; o4.z = 0.5f*z*(1.0f + erff(z*0.70710678118654752440f));
    z = dw*inv*gg.w + ee.w; o4.w = 0.5f*z*(1.0f + erff(z*0.70710678118654752440f));
    ((float4*)(Y + (size_t)row*INC))[tid] = o4;
}

// ---------------- K_ln2f: LN + GELU + w3 projection + mask + coarse --------
__global__ void __launch_bounds__(128) k_ln2f(
    const float* __restrict__ Xr, const float* __restrict__ gamma,
    const float* __restrict__ beta, const float* __restrict__ w3,
    const float* __restrict__ b3, const float* __restrict__ mask,
    float* __restrict__ rend)
{
    __shared__ float s[4];
    int row = blockIdx.x, tid = threadIdx.x;   // row = b*128 + n
    float2 t = ((const float2*)(Xr + (size_t)row*HID2))[tid];
    float sum = blk_reduce(t.x + t.y, s, tid);
    float m = sum * (1.0f/HID2);
    float dx = t.x-m, dy = t.y-m;
    float var = blk_reduce(dx*dx + dy*dy, s, tid);
    float inv = rsqrtf(var * (1.0f/HID2) + 1e-5f);
    float2 gg = ((const float2*)gamma)[tid];
    float2 ee = ((const float2*)beta)[tid];
    float z, hx, hy;
    z = dx*inv*gg.x + ee.x; hx = 0.5f*z*(1.0f + erff(z*0.70710678118654752440f));
    z = dy*inv*gg.y + ee.y; hy = 0.5f*z*(1.0f + erff(z*0.70710678118654752440f));
    float4 ww = ((const float4*)w3)[tid];
    float a0 = blk_reduce(hx*ww.x + hy*ww.z, s, tid);
    float a1 = blk_reduce(hx*ww.y + hy*ww.w, s, tid);
    if (tid == 0) {
        int b = row >> 7, n = row & 127;
        float c0 = g_feat[(size_t)row*KFP + 0];
        float c1 = g_feat[(size_t)row*KFP + 1];
        float m0 = mask[(size_t)(b*COUT + 0)*NPTS + n];
        float m1 = mask[(size_t)(b*COUT + 1)*NPTS + n];
        rend[(size_t)(b*COUT + 0)*NPTS + n] = (a0 + b3[0])*m0 + c0;
        rend[(size_t)(b*COUT + 1)*NPTS + n] = (a1 + b3[1])*m1 + c1;
    }
}

// ---------------- launch ----------------
extern "C" void kernel_launch(void* const* d_in, const int* in_sizes, int n_in,
                              void* d_out, int out_size)
{
    const float* res2       = (const float*)d_in[1];
    const float* out        = (const float*)d_in[2];
    const float* over_gen   = (const float*)d_in[3];
    const float* rand_point = (const float*)d_in[4];
    const float* mask       = (const float*)d_in[5];
    const float* w1  = (const float*)d_in[6];
    const float* b1  = (const float*)d_in[7];
    const float* g1  = (const float*)d_in[8];
    const float* be1 = (const float*)d_in[9];
    const float* w2  = (const float*)d_in[10];
    const float* b2  = (const float*)d_in[11];
    const float* g2  = (const float*)d_in[12];
    const float* be2 = (const float*)d_in[13];
    const float* w3  = (const float*)d_in[14];
    const float* b3  = (const float*)d_in[15];

    float* o_rend = (float*)d_out;                      // [8,2,128]
    float* o_pts  = o_rend + (size_t)BATCH*COUT*NPTS;   // [8,128,2]

    float* gf;  cudaGetSymbolAddress((void**)&gf,  g_feat);
    float* gt1; cudaGetSymbolAddress((void**)&gt1, g_t1);
    float* gh1; cudaGetSymbolAddress((void**)&gh1, g_h1);
    float* gt2; cudaGetSymbolAddress((void**)&gt2, g_t2);

    k_points<<<BATCH, NOG>>>(out, over_gen, rand_point, o_pts);
    k_feat  <<<BATCH*NPTS, 128>>>(out, res2);

    dim3 g1g(INC/64, NROWS/64);
    k_gemm<KFEAT, KFP, KFP, INC, 64, 4><<<g1g, 256>>>(gf, w1, b1, gt1);
    k_ln1<<<NROWS, 128>>>(gt1, g1, be1, gh1);

    dim3 g2g(HID2/64, NROWS/32);
    k_gemm<INC, INC, INC, HID2, 32, 2><<<g2g, 256>>>(gh1, w2, b2, gt2);
    k_ln2f<<<NROWS, 128>>>(gt2, g2, be2, w3, b3, mask, o_rend);
}

// round 6
// speedup vs baseline: 1.5116x; 1.5116x over previous
#include <cuda_runtime.h>
#include <math.h>

#define BATCH 8
#define HF    128
#define PIX   (HF*HF)
#define NOG   384
#define NIMP  96
#define NPTS  128
#define INC   512
#define HID2  256
#define KFEAT 514
#define KFP   528
#define COUT  2
#define NROWS (BATCH*NPTS) // 1024

// ---------------- scratch ----------------
__device__ float g_points[BATCH*NPTS*2];
__device__ float g_feat  [NROWS*KFP];
__device__ float g_t1    [NROWS*INC];
__device__ float g_h1    [NROWS*INC];
__device__ float g_t2    [NROWS*HID2];

// ---------------- bilinear helper ----------------
struct Bilin { int l00,l10,l01,l11; float w00,w10,w01,w11; };

__device__ __forceinline__ Bilin make_bilin(float px, float py) {
    Bilin r;
    float gx = ((2.0f*px - 1.0f + 1.0f)*(float)HF - 1.0f)*0.5f;
    float gy = ((2.0f*py - 1.0f + 1.0f)*(float)HF - 1.0f)*0.5f;
    float x0f = floorf(gx), y0f = floorf(gy);
    float wx1 = gx - x0f,  wy1 = gy - y0f;
    float wx0 = 1.0f - wx1, wy0 = 1.0f - wy1;
    int x0 = (int)x0f, y0 = (int)y0f;
    int x1 = x0 + 1,   y1 = y0 + 1;
    bool vx0 = (x0 >= 0) && (x0 <= HF-1);
    bool vx1 = (x1 >= 0) && (x1 <= HF-1);
    bool vy0 = (y0 >= 0) && (y0 <= HF-1);
    bool vy1 = (y1 >= 0) && (y1 <= HF-1);
    int x0c = min(max(x0,0),HF-1), x1c = min(max(x1,0),HF-1);
    int y0c = min(max(y0,0),HF-1), y1c = min(max(y1,0),HF-1);
    r.l00 = y0c*HF + x0c;  r.l10 = y0c*HF + x1c;
    r.l01 = y1c*HF + x0c;  r.l11 = y1c*HF + x1c;
    r.w00 = (vx0 && vy0) ? wx0*wy0 : 0.0f;
    r.w10 = (vx1 && vy0) ? wx1*wy0 : 0.0f;
    r.w01 = (vx0 && vy1) ? wx0*wy1 : 0.0f;
    r.w11 = (vx1 && vy1) ? wx1*wy1 : 0.0f;
    return r;
}

// ---------------- K1: sampling points ----------------
__global__ void __launch_bounds__(NOG) k_points(
    const float* __restrict__ out, const float* __restrict__ over_gen,
    const float* __restrict__ rand_point, float* __restrict__ pts_out)
{
    int b = blockIdx.x, tid = threadIdx.x;
    __shared__ float s_unc[NOG];
    const float* ob = out + (size_t)b*2*PIX;

    float px = over_gen[((size_t)b*NOG + tid)*2 + 0];
    float py = over_gen[((size_t)b*NOG + tid)*2 + 1];
    {
        Bilin bl = make_bilin(px, py);
        float a00 = ob[bl.l00], b00 = ob[PIX + bl.l00];
        float a10 = ob[bl.l10], b10 = ob[PIX + bl.l10];
        float a01 = ob[bl.l01], b01 = ob[PIX + bl.l01];
        float a11 = ob[bl.l11], b11 = ob[PIX + bl.l11];
        float og0 = bl.w00*fmaxf(a00,b00) + bl.w10*fmaxf(a10,b10)
                  + bl.w01*fmaxf(a01,b01) + bl.w11*fmaxf(a11,b11);
        float og1 = bl.w00*fminf(a00,b00) + bl.w10*fminf(a10,b10)
                  + bl.w01*fminf(a01,b01) + bl.w11*fminf(a11,b11);
        s_unc[tid] = og1 - og0;
    }
    __syncthreads();
    {
        float u = s_unc[tid];
        int rank = 0;
        #pragma unroll 8
        for (int j = 0; j < NOG; j++) {
            float uj = s_unc[j];
            rank += (uj > u) || (uj == u && j < tid);   // stable
        }
        if (rank < NIMP) {
            float2 p = make_float2(px, py);
            ((float2*)g_points)[b*NPTS + rank] = p;
            ((float2*)pts_out )[b*NPTS + rank] = p;
        }
    }
    if (tid < 16) {
        float2 z = make_float2(0.f, 0.f);
        ((float2*)g_points)[b*NPTS + NIMP + tid] = z;
        ((float2*)pts_out )[b*NPTS + NIMP + tid] = z;
        float2 rp = ((const float2*)rand_point)[b*16 + tid];
        ((float2*)g_points)[b*NPTS + NIMP + 16 + tid] = rp;
        ((float2*)pts_out )[b*NPTS + NIMP + 16 + tid] = rp;
    }
}

// ---------------- K2: gather feat rows ----------------
__global__ void __launch_bounds__(128) k_feat(
    const float* __restrict__ out, const float* __restrict__ res2)
{
    int idx = blockIdx.x;            // b*128 + n
    int b = idx >> 7;
    int tid = threadIdx.x;
    float2 p = ((const float2*)g_points)[idx];
    Bilin bl = make_bilin(p.x, p.y);
    const float* rb = res2 + (size_t)b*INC*PIX;
    float* frow = g_feat + (size_t)idx*KFP;

    #pragma unroll 4
    for (int c = tid; c < INC; c += 128) {
        const float* pp = rb + (size_t)c*PIX;
        frow[2 + c] = bl.w00*pp[bl.l00] + bl.w10*pp[bl.l10]
                    + bl.w01*pp[bl.l01] + bl.w11*pp[bl.l11];
    }
    if (tid < 2) {
        const float* pp = out + (size_t)(b*2 + tid)*PIX;
        frow[tid] = bl.w00*pp[bl.l00] + bl.w10*pp[bl.l10]
                  + bl.w01*pp[bl.l01] + bl.w11*pp[bl.l11];
    }
    if (tid >= 2 && tid < 16) frow[512 + tid] = 0.0f;
}

// ---------------- SGEMM + bias, double-buffered, packed f32x2 over N -------
// Layout identical to the 97us round-4 kernel; only the MAC section packs
// accumulator pairs over adjacent N columns (w pair = consecutive floats in
// sW, loaded by the same LDS.128; a broadcast-packed via mov.b64 {a,a}).
#define FMA2(d,a,b) asm("fma.rn.f32x2 %0, %1, %2, %0;" \
                        : "+l"(d) : "l"(a), "l"(b))

template<int KREAL, int KP, int LDA, int N, int BM, int TM>
__global__ void __launch_bounds__(256) k_gemm(
    const float* __restrict__ A, const float* __restrict__ W,
    const float* __restrict__ bias, float* __restrict__ C)
{
    constexpr int BK = 16, BN = 64;
    constexpr int KT = KP / BK;
    __shared__ float sA[2][BK][BM + 4];
    __shared__ float sW[2][BK][BN];

    int tid = threadIdx.x;
    int tx = tid & 15, ty = tid >> 4;
    int row0 = blockIdx.y * BM, col0 = blockIdx.x * BN;

    int a_m = tid >> 2, a_k = (tid & 3) * 4;
    int w_k = tid >> 4, w_n = (tid & 15) * 4;
    const bool aload = (BM * 4 == 256) || (tid < BM * 4);

    float4 av = make_float4(0,0,0,0), wv;
    if (aload) av = *(const float4*)&A[(size_t)(row0 + a_m)*LDA + a_k];
    wv = (w_k < KREAL) ? *(const float4*)&W[(size_t)w_k*N + col0 + w_n]
                       : make_float4(0,0,0,0);
    if (aload) {
        sA[0][a_k+0][a_m] = av.x; sA[0][a_k+1][a_m] = av.y;
        sA[0][a_k+2][a_m] = av.z; sA[0][a_k+3][a_m] = av.w;
    }
    *(float4*)&sW[0][w_k][w_n] = wv;
    __syncthreads();

    unsigned long long acc2[TM][2];   // col pairs {tx*4+0,+1} and {+2,+3}
    #pragma unroll
    for (int i = 0; i < TM; i++) { acc2[i][0] = 0ull; acc2[i][1] = 0ull; }

    for (int t = 0; t < KT; t++) {
        int buf = t & 1;
        if (t + 1 < KT) {
            int k0 = (t + 1) * BK;
            if (aload) av = *(const float4*)&A[(size_t)(row0 + a_m)*LDA + k0 + a_k];
            int kg = k0 + w_k;
            wv = (kg < KREAL) ? *(const float4*)&W[(size_t)kg*N + col0 + w_n]
                              : make_float4(0,0,0,0);
        }
        #pragma unroll
        for (int kk = 0; kk < BK; kk++) {
            float a[TM];
            if (TM == 4) {
                float4 v = *(const float4*)&sA[buf][kk][ty*4];
                a[0]=v.x; a[1]=v.y; a[2]=v.z; a[3]=v.w;
            } else {
                float2 v = *(const float2*)&sA[buf][kk][ty*2];
                a[0]=v.x; a[1]=v.y;
            }
            ulonglong2 wp = *(const ulonglong2*)&sW[buf][kk][tx*4];
            #pragma unroll
            for (int i = 0; i < TM; i++) {
                unsigned long long ad;
                asm("mov.b64 %0, {%1, %1};" : "=l"(ad) : "f"(a[i]));
                FMA2(acc2[i][0], ad, wp.x);
                FMA2(acc2[i][1], ad, wp.y);
            }
        }
        if (t + 1 < KT) {
            int nb = buf ^ 1;
            if (aload) {
                sA[nb][a_k+0][a_m] = av.x; sA[nb][a_k+1][a_m] = av.y;
                sA[nb][a_k+2][a_m] = av.z; sA[nb][a_k+3][a_m] = av.w;
            }
            *(float4*)&sW[nb][w_k][w_n] = wv;
            __syncthreads();
        }
    }

    float4 bv = *(const float4*)&bias[col0 + tx*4];
    #pragma unroll
    for (int i = 0; i < TM; i++) {
        float c0, c1, c2, c3;
        asm("mov.b64 {%0, %1}, %2;" : "=f"(c0), "=f"(c1) : "l"(acc2[i][0]));
        asm("mov.b64 {%0, %1}, %2;" : "=f"(c2), "=f"(c3) : "l"(acc2[i][1]));
        float4 v = make_float4(c0 + bv.x, c1 + bv.y, c2 + bv.z, c3 + bv.w);
        *(float4*)&C[(size_t)(row0 + ty*TM + i)*N + col0 + tx*4] = v;
    }
}

// ---------------- block reduce (128 threads / 4 warps) ---------------------
__device__ __forceinline__ float blk_reduce(float v, float* s, int tid) {
    int lane = tid & 31, warp = tid >> 5;
    #pragma unroll
    for (int o = 16; o; o >>= 1) v += __shfl_xor_sync(0xffffffff, v, o);
    if (lane == 0) s[warp] = v;
    __syncthreads();
    float r = s[0] + s[1] + s[2] + s[3];
    __syncthreads();
    return r;
}

// ---------------- K_ln1: LN + exact GELU (block per row) -------------------
__global__ void __launch_bounds__(128) k_ln1(
    const float* __restrict__ Xr, const float* __restrict__ gamma,
    const float* __restrict__ beta, float* __restrict__ Y)
{
    __shared__ float s[4];
    int row = blockIdx.x, tid = threadIdx.x;
    float4 t = ((const float4*)(Xr + (size_t)row*INC))[tid];
    float sum = blk_reduce(t.x + t.y + t.z + t.w, s, tid);
    float m = sum * (1.0f/INC);
    float dx = t.x-m, dy = t.y-m, dz = t.z-m, dw = t.w-m;
    float var = blk_reduce(dx*dx + dy*dy + dz*dz + dw*dw, s, tid);
    float inv = rsqrtf(var * (1.0f/INC) + 1e-5f);
    float4 gg = ((const float4*)gamma)[tid];
    float4 ee = ((const float4*)beta)[tid];
    float4 o4; float z;
    z = dx*inv*gg.x + ee.x; o4.x = 0.5f*z*(1.0f + erff(z*0.70710678118654752440f));
    z = dy*inv*gg.y + ee.y; o4.y = 0.5f*z*(1.0f + erff(z*0.70710678118654752440f));
    z = dz*inv*gg.z + ee.z; o4.z = 0.5f*z*(1.0f + erff(z*0.70710678118654752440f));
    z = dw*inv*gg.w + ee.w; o4.w = 0.5f*z*(1.0f + erff(z*0.70710678118654752440f));
    ((float4*)(Y + (size_t)row*INC))[tid] = o4;
}

// ---------------- K_ln2f: LN + GELU + w3 projection + mask + coarse --------
__global__ void __launch_bounds__(128) k_ln2f(
    const float* __restrict__ Xr, const float* __restrict__ gamma,
    const float* __restrict__ beta, const float* __restrict__ w3,
    const float* __restrict__ b3, const float* __restrict__ mask,
    float* __restrict__ rend)
{
    __shared__ float s[4];
    int row = blockIdx.x, tid = threadIdx.x;   // row = b*128 + n
    float2 t = ((const float2*)(Xr + (size_t)row*HID2))[tid];
    float sum = blk_reduce(t.x + t.y, s, tid);
    float m = sum * (1.0f/HID2);
    float dx = t.x-m, dy = t.y-m;
    float var = blk_reduce(dx*dx + dy*dy, s, tid);
    float inv = rsqrtf(var * (1.0f/HID2) + 1e-5f);
    float2 gg = ((const float2*)gamma)[tid];
    float2 ee = ((const float2*)beta)[tid];
    float z, hx, hy;
    z = dx*inv*gg.x + ee.x; hx = 0.5f*z*(1.0f + erff(z*0.70710678118654752440f));
    z = dy*inv*gg.y + ee.y; hy = 0.5f*z*(1.0f + erff(z*0.70710678118654752440f));
    float4 ww = ((const float4*)w3)[tid];
    float a0 = blk_reduce(hx*ww.x + hy*ww.z, s, tid);
    float a1 = blk_reduce(hx*ww.y + hy*ww.w, s, tid);
    if (tid == 0) {
        int b = row >> 7, n = row & 127;
        float c0 = g_feat[(size_t)row*KFP + 0];
        float c1 = g_feat[(size_t)row*KFP + 1];
        float m0 = mask[(size_t)(b*COUT + 0)*NPTS + n];
        float m1 = mask[(size_t)(b*COUT + 1)*NPTS + n];
        rend[(size_t)(b*COUT + 0)*NPTS + n] = (a0 + b3[0])*m0 + c0;
        rend[(size_t)(b*COUT + 1)*NPTS + n] = (a1 + b3[1])*m1 + c1;
    }
}

// ---------------- launch ----------------
extern "C" void kernel_launch(void* const* d_in, const int* in_sizes, int n_in,
                              void* d_out, int out_size)
{
    const float* res2       = (const float*)d_in[1];
    const float* out        = (const float*)d_in[2];
    const float* over_gen   = (const float*)d_in[3];
    const float* rand_point = (const float*)d_in[4];
    const float* mask       = (const float*)d_in[5];
    const float* w1  = (const float*)d_in[6];
    const float* b1  = (const float*)d_in[7];
    const float* g1  = (const float*)d_in[8];
    const float* be1 = (const float*)d_in[9];
    const float* w2  = (const float*)d_in[10];
    const float* b2  = (const float*)d_in[11];
    const float* g2  = (const float*)d_in[12];
    const float* be2 = (const float*)d_in[13];
    const float* w3  = (const float*)d_in[14];
    const float* b3  = (const float*)d_in[15];

    float* o_rend = (float*)d_out;                      // [8,2,128]
    float* o_pts  = o_rend + (size_t)BATCH*COUT*NPTS;   // [8,128,2]

    float* gf;  cudaGetSymbolAddress((void**)&gf,  g_feat);
    float* gt1; cudaGetSymbolAddress((void**)&gt1, g_t1);
    float* gh1; cudaGetSymbolAddress((void**)&gh1, g_h1);
    float* gt2; cudaGetSymbolAddress((void**)&gt2, g_t2);

    k_points<<<BATCH, NOG>>>(out, over_gen, rand_point, o_pts);
    k_feat  <<<BATCH*NPTS, 128>>>(out, res2);

    dim3 g1g(INC/64, NROWS/64);
    k_gemm<KFEAT, KFP, KFP, INC, 64, 4><<<g1g, 256>>>(gf, w1, b1, gt1);
    k_ln1<<<NROWS, 128>>>(gt1, g1, be1, gh1);

    dim3 g2g(HID2/64, NROWS/32);
    k_gemm<INC, INC, INC, HID2, 32, 2><<<g2g, 256>>>(gh1, w2, b2, gt2);
    k_ln2f<<<NROWS, 128>>>(gt2, g2, be2, w3, b3, mask, o_rend);
}